// round 15
// baseline (speedup 1.0000x reference)
#include <cuda_runtime.h>
#include <cuda_bf16.h>
#include <cstdint>
#include <math.h>

#define TT    1024
#define BB    64
#define HH    512
#define HIDD  512
#define NG    2048           // 4*HID
#define NROWS 65536          // T*B

// ------------------------- scratch (static device memory; no allocs) -------------------------
// Z layout: [t][n-slice(64)][b(64)][40]  (32 gate-cols + 8 pad, per 8-hid slice)
static __device__ float d_Zf [(size_t)TT * 64 * 64 * 40];
static __device__ float d_Zb [(size_t)TT * 64 * 64 * 40];
static __device__ unsigned short d_Yh [(size_t)NROWS * HH];
static __device__ unsigned short d_Yl [(size_t)NROWS * HH];
static __device__ unsigned short d_Yrh[(size_t)NROWS * HH];
static __device__ unsigned short d_Yrl[(size_t)NROWS * HH];
static __device__ unsigned short d_Wxh[2][NG * HH];    // [n'][k] gate-interleaved bf16 hi
static __device__ unsigned short d_Wxl[2][NG * HH];    // lo
static __device__ unsigned short d_Whh[2][NG * HH];    // Wh bf16 hi
static __device__ unsigned short d_Whl[2][NG * HH];    // Wh bf16 lo
static __device__ float d_brd[2][NG];
// h transport: [dir][buf][4 chunks][hi 64x128 | lo 64x128] bf16, swizzled for ldmatrix
static __device__ unsigned short d_hA[2][2][65536];
static __device__ float d_ps [128 * 512];
static __device__ float d_ps2[128 * 512];
static __device__ float d_an[HH];
static __device__ float d_b2[HH];
static __device__ unsigned d_scnt;
static __device__ unsigned d_cnt[8][32];               // per (dir,chunk) publish counters, 128B-padded
static __device__ unsigned d_done;

__device__ __forceinline__ float sigm(float x) { return 1.0f / (1.0f + __expf(-x)); }

__device__ __forceinline__ uint32_t smem_u32(const void* p) {
    uint32_t a;
    asm("{ .reg .u64 t; cvta.to.shared.u64 t, %1; cvt.u32.u64 %0, t; }" : "=r"(a) : "l"(p));
    return a;
}

__device__ __forceinline__ void cpa16(uint32_t dst, const void* src) {
    asm volatile("cp.async.cg.shared.global [%0], [%1], 16;" :: "r"(dst), "l"(src));
}
#define CPA_COMMIT() asm volatile("cp.async.commit_group;" ::: "memory")
#define CPA_WAIT1()  asm volatile("cp.async.wait_group 1;" ::: "memory")
#define CPA_WAIT0()  asm volatile("cp.async.wait_group 0;" ::: "memory")

__device__ __forceinline__ void ldsm4(uint32_t* d, uint32_t a) {
    asm volatile("ldmatrix.sync.aligned.m8n8.x4.shared.b16 {%0,%1,%2,%3}, [%4];"
                 : "=r"(d[0]), "=r"(d[1]), "=r"(d[2]), "=r"(d[3]) : "r"(a));
}
__device__ __forceinline__ void ldsm2(uint32_t* d, uint32_t a) {
    asm volatile("ldmatrix.sync.aligned.m8n8.x2.shared.b16 {%0,%1}, [%2];"
                 : "=r"(d[0]), "=r"(d[1]) : "r"(a));
}
__device__ __forceinline__ void mma16816(float* d, const uint32_t* a, const uint32_t* b) {
    asm volatile("mma.sync.aligned.m16n8k16.row.col.f32.bf16.bf16.f32 "
                 "{%0,%1,%2,%3}, {%4,%5,%6,%7}, {%8,%9}, {%0,%1,%2,%3};"
                 : "+f"(d[0]), "+f"(d[1]), "+f"(d[2]), "+f"(d[3])
                 : "r"(a[0]), "r"(a[1]), "r"(a[2]), "r"(a[3]), "r"(b[0]), "r"(b[1]));
}
__device__ __forceinline__ void redadd(float* p, float v) {
    asm volatile("red.global.add.f32 [%0], %1;" :: "l"(p), "f"(v) : "memory");
}
__device__ __forceinline__ void red_release_inc(unsigned* p) {
    asm volatile("red.release.gpu.global.add.u32 [%0], 1;" :: "l"(p) : "memory");
}

__device__ __forceinline__ void mbar_init(uint32_t m) {
    asm volatile("mbarrier.init.shared.b64 [%0], 1;" :: "r"(m) : "memory");
}
__device__ __forceinline__ void mbar_expect(uint32_t m, uint32_t bytes) {
    asm volatile("mbarrier.arrive.expect_tx.shared.b64 _, [%0], %1;"
                 :: "r"(m), "r"(bytes) : "memory");
}
__device__ __forceinline__ void mbar_wait(uint32_t m, uint32_t ph) {
    asm volatile(
        "{\n\t.reg .pred P;\n\tLW%=:\n\t"
        "mbarrier.try_wait.parity.acquire.cta.shared::cta.b64 P, [%0], %1;\n\t"
        "@!P bra LW%=;\n\t}"
        :: "r"(m), "r"(ph) : "memory");
}
__device__ __forceinline__ void bulk_g2s(uint32_t dst, const void* src, uint32_t bytes,
                                         uint32_t mbar) {
    asm volatile(
        "cp.async.bulk.shared::cluster.global.mbarrier::complete_tx::bytes [%0], [%1], %2, [%3];"
        :: "r"(dst), "l"(src), "r"(bytes), "r"(mbar) : "memory");
}

// ------------------- prepfin: stats partials + last-block finalize + weight reorder ----------
__global__ void k_prepfin(const float* __restrict__ x,
                          const float* __restrict__ Wxf, const float* __restrict__ Whf,
                          const float* __restrict__ Wxb, const float* __restrict__ Whb,
                          const float* __restrict__ bf,  const float* __restrict__ bb,
                          const int* __restrict__ lengths, const float* __restrict__ scale,
                          const float* __restrict__ bias, const int* __restrict__ training) {
    int bx = blockIdx.x, tid = threadIdx.x;     // 256 threads
    if (bx < 128) {
        size_t r0 = (size_t)bx * 512;
        float s0 = 0, s20 = 0, s1 = 0, s21 = 0;
        for (int r = 0; r < 512; r++) {
            float v0 = x[(r0 + r) * 512 + tid];
            float v1 = x[(r0 + r) * 512 + tid + 256];
            s0 += v0; s20 += v0 * v0;
            s1 += v1; s21 += v1 * v1;
        }
        d_ps [bx * 512 + tid]       = s0;
        d_ps [bx * 512 + tid + 256] = s1;
        d_ps2[bx * 512 + tid]       = s20;
        d_ps2[bx * 512 + tid + 256] = s21;
        __threadfence();
        __syncthreads();
        __shared__ int s_last;
        __shared__ float s_nz;
        if (tid == 0) {
            unsigned old = atomicAdd(&d_scnt, 1u);
            s_last = (old == 127u);
            if (s_last) {
                int s = 0;
                for (int b = 0; b < BB; b++) s += lengths[b];
                s_nz = (float)s;
            }
        }
        __syncthreads();
        if (s_last) {
            __threadfence();
            int tr = *training;
#pragma unroll
            for (int cc = 0; cc < 2; cc++) {
                int c = tid + cc * 256;
                float s = 0.0f, s2 = 0.0f;
#pragma unroll 4
                for (int p = 0; p < 128; p++) {
                    s  += d_ps [p * 512 + c];
                    s2 += d_ps2[p * 512 + c];
                }
                float mean, var;
                if (tr) {
                    mean = s / s_nz;
                    float m2 = s2 / s_nz;
                    var = fmaxf(0.0f, m2 - mean * mean);
                } else {
                    mean = 0.0f; var = 1.0f;
                }
                float a = rsqrtf(var + 1e-5f) * scale[c];
                d_an[c] = a;
                d_b2[c] = bias[c] - mean * a;
            }
            __syncthreads();
            if (tid == 0) { __threadfence(); d_scnt = 0u; }
        }
    } else {
        int idx = (bx - 128) * 256 + tid;       // [0, 4M)
        int z = idx >> 20;
        int i = idx & 0xFFFFF;
        const float* src = (z == 0) ? Wxf : (z == 1) ? Whf : (z == 2) ? Wxb : Whb;
        unsigned short* dh = (z == 0) ? d_Wxh[0] : (z == 1) ? d_Whh[0]
                           : (z == 2) ? d_Wxh[1] : d_Whh[1];
        unsigned short* dl = (z == 0) ? d_Wxl[0] : (z == 1) ? d_Whl[0]
                           : (z == 2) ? d_Wxl[1] : d_Whl[1];
        int k = i & 511, nn = i >> 9;
        int g = nn & 3, j = nn >> 2;
        float v = src[(k << 11) + (g << 9) + j];
        __nv_bfloat16 h = __float2bfloat16_rn(v);
        float lo = v - __bfloat162float(h);
        dh[i] = __bfloat16_as_ushort(h);
        dl[i] = __bfloat16_as_ushort(__float2bfloat16_rn(lo));
        if (i < NG) {
            if (z == 0) d_brd[0][i] = bf[((i & 3) << 9) + (i >> 2)];
            else if (z == 2) d_brd[1][i] = bb[((i & 3) << 9) + (i >> 2)];
        }
    }
}

// ------------------------- BN apply + mask + bf16 split + flip + out zero -------------------
__global__ void k_bnapply(const float* __restrict__ x, const float* __restrict__ mask,
                          const int* __restrict__ lengths, float* __restrict__ out) {
    int i = blockIdx.x * 256 + threadIdx.x;
    *(float4*)(out + (size_t)i * 4) = make_float4(0.f, 0.f, 0.f, 0.f);

    int row = i >> 7;
    int c4  = (i & 127) << 2;
    int t = row >> 6, b = row & 63;
    float4 xv = *(const float4*)(x + ((size_t)row << 9) + c4);
    float4 av = *(const float4*)(d_an + c4);
    float4 bv = *(const float4*)(d_b2 + c4);
    float m = __ldg(mask + row);
    float y[4];
    y[0] = (xv.x * av.x + bv.x) * m;
    y[1] = (xv.y * av.y + bv.y) * m;
    y[2] = (xv.z * av.z + bv.z) * m;
    y[3] = (xv.w * av.w + bv.w) * m;
    uint2 hv, lv;
    unsigned hs[4], ls[4];
#pragma unroll
    for (int q = 0; q < 4; q++) {
        __nv_bfloat16 h = __float2bfloat16_rn(y[q]);
        float lo = y[q] - __bfloat162float(h);
        hs[q] = __bfloat16_as_ushort(h);
        ls[q] = __bfloat16_as_ushort(__float2bfloat16_rn(lo));
    }
    hv.x = hs[0] | (hs[1] << 16); hv.y = hs[2] | (hs[3] << 16);
    lv.x = ls[0] | (ls[1] << 16); lv.y = ls[2] | (ls[3] << 16);
    size_t o = ((size_t)row << 9) + c4;
    *(uint2*)(d_Yh + o) = hv;
    *(uint2*)(d_Yl + o) = lv;
    int l = __ldg(lengths + b);
    if (t < l) {
        size_t orr = ((size_t)((l - 1 - t) * BB + b) << 9) + c4;
        *(uint2*)(d_Yrh + orr) = hv;
        *(uint2*)(d_Yrl + orr) = lv;
    } else {
        *(uint2*)(d_Yrh + o) = make_uint2(0u, 0u);
        *(uint2*)(d_Yrl + o) = make_uint2(0u, 0u);
    }
}

// ------------------------- HMMA split-bf16 GEMM v2: 256x128 tiles, 512 threads --------------
// A traffic halves vs 128x128 (L2-bound kernel). Stage = A 32KB (hi|lo) + B 16KB.
#define STAGE2 49152
__global__ __launch_bounds__(512) void k_hgemm() {
    extern __shared__ char dsm[];
    uint32_t sb = (smem_u32(dsm) + 127) & ~127u;
    float* cs = (float*)(dsm + (sb - smem_u32(dsm)));
    int tid = threadIdx.x;
    int lane = tid & 31, wid = tid >> 5;       // 16 warps: 4m x 4n
    int wm0 = (wid >> 2) * 64;
    int wn0 = (wid & 3) * 32;
    int n0 = blockIdx.x * 128;
    int m0 = blockIdx.y * 256;
    int dir = blockIdx.z;

    const unsigned short* Ah = (dir ? d_Yrh : d_Yh) + (size_t)m0 * 512;
    const unsigned short* Al = (dir ? d_Yrl : d_Yl) + (size_t)m0 * 512;
    const unsigned short* Bh = d_Wxh[dir] + (size_t)n0 * 512;
    const unsigned short* Bl = d_Wxl[dir] + (size_t)n0 * 512;

    float acc[4][4][4];
#pragma unroll
    for (int a = 0; a < 4; a++)
#pragma unroll
        for (int b = 0; b < 4; b++)
#pragma unroll
            for (int c = 0; c < 4; c++) acc[a][b][c] = 0.0f;

    auto load_chunk = [&](int s, int k0) {
        uint32_t bA = sb + s * STAGE2, bB = bA + 32768;
#pragma unroll
        for (int it = 0; it < 4; it++) {       // A: 256 rows x 8 16B-cols = 2048 ops
            int q = tid + it * 512;
            int r = q >> 3, c = q & 7;
            uint32_t sw = (uint32_t)r * 128 + (uint32_t)((c ^ (r & 7)) << 4);
            cpa16(bA + sw, (c < 4) ? (const void*)(Ah + (size_t)r * 512 + k0 + c * 8)
                                   : (const void*)(Al + (size_t)r * 512 + k0 + (c - 4) * 8));
        }
#pragma unroll
        for (int it = 0; it < 2; it++) {       // B: 128 rows x 8 = 1024 ops
            int q = tid + it * 512;
            int r = q >> 3, c = q & 7;
            uint32_t sw = (uint32_t)r * 128 + (uint32_t)((c ^ (r & 7)) << 4);
            cpa16(bB + sw, (c < 4) ? (const void*)(Bh + (size_t)r * 512 + k0 + c * 8)
                                   : (const void*)(Bl + (size_t)r * 512 + k0 + (c - 4) * 8));
        }
    };

    load_chunk(0, 0);  CPA_COMMIT();
    load_chunk(1, 32); CPA_COMMIT();

    for (int i = 0; i < 16; i++) {
        if (i < 15) CPA_WAIT1(); else CPA_WAIT0();
        __syncthreads();
        uint32_t bA = sb + (i & 1) * STAGE2, bB = bA + 32768;
#pragma unroll
        for (int ks = 0; ks < 2; ks++) {
            uint32_t ah[4][4], al[4][4];
#pragma unroll
            for (int mf = 0; mf < 4; mf++) {
                int r = wm0 + mf * 16 + (lane & 15);
                int ch = 2 * ks + (lane >> 4);
                ldsm4(ah[mf], bA + r * 128 + ((ch       ^ (r & 7)) << 4));
                ldsm4(al[mf], bA + r * 128 + (((ch + 4) ^ (r & 7)) << 4));
            }
#pragma unroll
            for (int nf = 0; nf < 4; nf++) {
                int rb = wn0 + nf * 8 + (lane & 7);
                int cb = 2 * ks + ((lane >> 3) & 1);
                uint32_t bh[2], bl[2];
                ldsm2(bh, bB + rb * 128 + ((cb       ^ (rb & 7)) << 4));
                ldsm2(bl, bB + rb * 128 + (((cb + 4) ^ (rb & 7)) << 4));
#pragma unroll
                for (int mf = 0; mf < 4; mf++) {
                    mma16816(acc[mf][nf], ah[mf], bh);
                    mma16816(acc[mf][nf], ah[mf], bl);
                    mma16816(acc[mf][nf], al[mf], bh);
                }
            }
        }
        __syncthreads();
        if (i + 2 < 16) { load_chunk(i & 1, (i + 2) * 32); CPA_COMMIT(); }
    }

    // stage into smem [256 rows][132] with bias
    const float* bias = d_brd[dir];
#pragma unroll
    for (int nf = 0; nf < 4; nf++) {
        int gc = wn0 + nf * 8 + (lane & 3) * 2;
        float b0 = __ldg(bias + n0 + gc), b1 = __ldg(bias + n0 + gc + 1);
#pragma unroll
        for (int mf = 0; mf < 4; mf++) {
            int r = wm0 + mf * 16 + (lane >> 2);
            cs[r * 132 + gc]             = acc[mf][nf][0] + b0;
            cs[r * 132 + gc + 1]         = acc[mf][nf][1] + b1;
            cs[(r + 8) * 132 + gc]       = acc[mf][nf][2] + b0;
            cs[(r + 8) * 132 + gc + 1]   = acc[mf][nf][3] + b1;
        }
    }
    __syncthreads();

    // write Z[t][nslice][b][40] (4 t-blocks)
    float* Z = dir ? d_Zb : d_Zf;
    int t0 = m0 >> 6;
    int nb0 = n0 >> 5;
#pragma unroll
    for (int p = 0; p < 16; p++) {
        int q = tid + p * 512;                 // 8192 float4
        int c4i = q & 7;
        int nq  = (q >> 3) & 3;
        int b   = (q >> 5) & 63;
        int th  = q >> 11;                     // 0..3
        float4 v = *(const float4*)(cs + (th * 64 + b) * 132 + nq * 32 + c4i * 4);
        *(float4*)(Z + ((size_t)(t0 + th) * 64 + nb0 + nq) * 2560 + b * 40 + c4i * 4) = v;
    }
}

// ------------------------- persistent LSTM v11: hi-first split DMA pipeline -----------------
// Per chunk: hi 16KB (own mbar) then lo 16KB (own mbar). MMA: wait-hi -> ah*bh + ah*bl
// (keeping bh regs) -> wait-lo -> al*bh (reusing bh regs).
// mbars: A-hi [4] @ mb+0..31, A-lo [4] @ mb+32..63, z [2] @ mb+64..79
#define LSMEM (226304 + 96)
__global__ __launch_bounds__(512) void k_lstm(float* __restrict__ out,
                                              const int* __restrict__ lengths) {
    extern __shared__ char sm[];
    uint32_t smb = smem_u32(sm);
    float* zacc = (float*)(sm + 217088);
    uint32_t mb = smb + 226304;

    int blk = blockIdx.x;
    int dir = blk >> 6;
    int n   = blk & 63;
    const float* __restrict__ Zx = dir ? d_Zb : d_Zf;

    int tid = threadIdx.x;
    int lane = tid & 31, w = tid >> 5;
    int mt = w & 3, nt = w >> 2;

    int tx = tid & 7;
    int ty = (tid >> 3) & 31;
    int j = n * 8 + tx;
    int r0 = ty * 2;
    int l0 = __ldg(lengths + r0);
    int l1 = __ldg(lengths + r0 + 1);

    // ---- load Wh (bf16 hi/lo) into swizzled smem B, once ----
    for (int i = tid; i < 2048; i += 512) {
        int c = i >> 6, kc = i & 63;
        int segp = (kc & ~7) | ((kc & 7) ^ (c & 7));
        const uint4* sh = (const uint4*)(d_Whh[dir] + ((size_t)(n * 32 + c) * 512 + kc * 8));
        const uint4* sl = (const uint4*)(d_Whl[dir] + ((size_t)(n * 32 + c) * 512 + kc * 8));
        *(uint4*)(sm + c * 1024 + segp * 16)         = *sh;
        *(uint4*)(sm + 32768 + c * 1024 + segp * 16) = *sl;
    }
    if (tid == 0) {
#pragma unroll
        for (int c = 0; c < 10; c++) mbar_init(mb + c * 8);
    }
    __syncthreads();

    if (tid == 0) {                                   // z(0) prefetch
        mbar_expect(mb + 64, 10240);
        bulk_g2s(smb + 196608, Zx + (size_t)n * 2560, 10240, mb + 64);
    }

    float cst0 = 0.0f, cst1 = 0.0f;

    // producer swizzle constants
    int segP0 = (n & 8) | ((n & 7) ^ (r0 & 7));
    int segP1 = (n & 8) | ((n & 7) ^ ((r0 + 1) & 7));
    int pchunk = (n >> 4) * 16384;
    unsigned* mycnt = &d_cnt[dir * 4 + (n >> 4)][0];

    for (int t = 0; t < TT; t++) {
        // parallel per-chunk gating + split DMA issue (threads 0-3), z prefetch (thread 4)
        if (t > 0 && tid < 4) {
            const unsigned* cp = &d_cnt[dir * 4 + tid][0];
            unsigned need = (unsigned)t * 16u;
            unsigned v;
            do {
                asm volatile("ld.acquire.gpu.u32 %0, [%1];" : "=r"(v) : "l"(cp) : "memory");
            } while (v < need);
            const unsigned short* hsrc = d_hA[dir][(t - 1) & 1] + tid * 16384;
            uint32_t dst = smb + 65536 + tid * 32768;
            mbar_expect(mb + tid * 8, 16384);
            bulk_g2s(dst, hsrc, 16384, mb + tid * 8);                      // hi first
            mbar_expect(mb + 32 + tid * 8, 16384);
            bulk_g2s(dst + 16384, hsrc + 8192, 16384, mb + 32 + tid * 8);  // lo second
        }
        if (tid == 4 && t + 1 < TT) {
            int s = (t + 1) & 1;
            mbar_expect(mb + 64 + s * 8, 10240);
            bulk_g2s(smb + 196608 + s * 10240,
                     Zx + ((size_t)(t + 1) * 64 + n) * 2560, 10240, mb + 64 + s * 8);
        }

        // ---- MMA phase (all 16 warps) ----
        if (t > 0) {
            float acc[4] = {0.f, 0.f, 0.f, 0.f};
            int r  = mt * 16 + (lane & 15);
            int cB = nt * 8 + (lane & 7);
            uint32_t rowA = smb + 65536 + (uint32_t)r * 256;
            uint32_t rowB = smb + (uint32_t)cB * 1024;
            uint32_t ph = (uint32_t)((t - 1) & 1);
#pragma unroll
            for (int c = 0; c < 4; c++) {
                uint32_t aHi = rowA + c * 32768;
                uint32_t aLo = aHi + 16384;
                uint32_t bh_all[16];
                // pass 1: hi terms (ah*bh, ah*bl), keep bh in regs
                mbar_wait(mb + c * 8, ph);
#pragma unroll
                for (int kt2 = 0; kt2 < 4; kt2++) {
                    int kcB = c * 16 + 4 * kt2 + (lane >> 3);
                    uint32_t segB = (uint32_t)((kcB & ~7) | ((kcB & 7) ^ (cB & 7))) << 4;
                    uint32_t bl[4];
                    ldsm4(bh_all + kt2 * 4, rowB + segB);
                    ldsm4(bl, rowB + 32768 + segB);
#pragma unroll
                    for (int ss = 0; ss < 2; ss++) {
                        int kcA = 4 * kt2 + 2 * ss + (lane >> 4);
                        uint32_t segA = (uint32_t)((kcA & 8) | ((kcA & 7) ^ (r & 7))) << 4;
                        uint32_t ah[4];
                        ldsm4(ah, aHi + segA);
                        mma16816(acc, ah, bh_all + kt2 * 4 + 2 * ss);
                        mma16816(acc, ah, bl + 2 * ss);
                    }
                }
                // pass 2: lo term (al*bh), bh reused from regs
                mbar_wait(mb + 32 + c * 8, ph);
#pragma unroll
                for (int kt2 = 0; kt2 < 4; kt2++) {
#pragma unroll
                    for (int ss = 0; ss < 2; ss++) {
                        int kcA = 4 * kt2 + 2 * ss + (lane >> 4);
                        uint32_t segA = (uint32_t)((kcA & 8) | ((kcA & 7) ^ (r & 7))) << 4;
                        uint32_t al[4];
                        ldsm4(al, aLo + segA);
                        mma16816(acc, al, bh_all + kt2 * 4 + 2 * ss);
                    }
                }
            }
            int rr = mt * 16 + (lane >> 2);
            int cc = nt * 8 + (lane & 3) * 2;
            *(float2*)(zacc + rr * 36 + cc)       = make_float2(acc[0], acc[1]);
            *(float2*)(zacc + (rr + 8) * 36 + cc) = make_float2(acc[2], acc[3]);
        }
        __syncthreads();

        // ---- epilogue (tid < 256) ----
        float hn0 = 0.f, hn1 = 0.f;
        if (tid < 256) {
            mbar_wait(mb + 64 + (t & 1) * 8, (uint32_t)((t >> 1) & 1));
            const float* zb = (const float*)(sm + 196608) + (t & 1) * 2560;
            float4 zf0 = *(const float4*)(zb + r0 * 40 + tx * 4);
            float4 zf1 = *(const float4*)(zb + (r0 + 1) * 40 + tx * 4);
            float4 zaA, zaB;
            if (t > 0) {
                zaA = *(const float4*)(zacc + r0 * 36 + tx * 4);
                zaB = *(const float4*)(zacc + (r0 + 1) * 36 + tx * 4);
            } else {
                zaA = make_float4(0.f, 0.f, 0.f, 0.f);
                zaB = zaA;
            }
            {
                float zi = zaA.x + zf0.x;
                float zf = zaA.y + zf0.y;
                float zg = zaA.z + zf0.z;
                float zo = zaA.w + zf0.w;
                float cn = sigm(zf) * cst0 + sigm(zi) * tanhf(zg);
                cst0 = cn;
                hn0 = sigm(zo) * tanhf(cn);
            }
            {
                float zi = zaB.x + zf1.x;
                float zf = zaB.y + zf1.y;
                float zg = zaB.z + zf1.z;
                float zo = zaB.w + zf1.w;
                float cn = sigm(zf) * cst1 + sigm(zi) * tanhf(zg);
                cst1 = cn;
                hn1 = sigm(zo) * tanhf(cn);
            }

            // publish h(t+1): bf16 hi/lo into pre-swizzled transport buffer
            unsigned short* hw = d_hA[dir][t & 1] + pchunk;
            __nv_bfloat16 h0 = __float2bfloat16_rn(hn0);
            __nv_bfloat16 h1 = __float2bfloat16_rn(hn1);
            float lo0 = hn0 - __bfloat162float(h0);
            float lo1 = hn1 - __bfloat162float(h1);
            hw[r0 * 128 + segP0 * 8 + tx]              = __bfloat16_as_ushort(h0);
            hw[(r0 + 1) * 128 + segP1 * 8 + tx]        = __bfloat16_as_ushort(h1);
            hw[8192 + r0 * 128 + segP0 * 8 + tx]       = __bfloat16_as_ushort(__float2bfloat16_rn(lo0));
            hw[8192 + (r0 + 1) * 128 + segP1 * 8 + tx] = __bfloat16_as_ushort(__float2bfloat16_rn(lo1));
        }

        // publish counter: bar.sync orders intra-CTA; release-atomic orders inter-CTA
        __syncthreads();
        if (tid == 0) red_release_inc(mycnt);

        // output accumulation off the critical path (no-return reductions)
        if (tid < 256) {
            if (dir == 0) {
                redadd(out + ((size_t)(t * BB + r0)) * HIDD + j, hn0);
                redadd(out + ((size_t)(t * BB + r0 + 1)) * HIDD + j, hn1);
            } else {
                int to0 = (t < l0) ? (l0 - 1 - t) : (TT - 1 + l0 - t);
                int to1 = (t < l1) ? (l1 - 1 - t) : (TT - 1 + l1 - t);
                redadd(out + ((size_t)(to0 * BB + r0)) * HIDD + j, hn0);
                redadd(out + ((size_t)(to1 * BB + r0 + 1)) * HIDD + j, hn1);
            }
        }
    }

    // self-reset for graph replay
    __syncthreads();
    if (tid == 0) {
        __threadfence();
        atomicAdd(&d_done, 1u);
        if (blk == 0) {
            volatile unsigned* vd = &d_done;
            while (*vd < 128u) { }
            for (int q = 0; q < 8; q++) d_cnt[q][0] = 0u;
            __threadfence();
            d_done = 0u;
        }
    }
}

// ------------------------- launch -------------------------
extern "C" void kernel_launch(void* const* d_in, const int* in_sizes, int n_in,
                              void* d_out, int out_size) {
    const float* x        = (const float*)d_in[0];
    const int*   lengths  = (const int*)  d_in[1];
    const float* mask     = (const float*)d_in[2];
    const float* scale    = (const float*)d_in[3];
    const float* bias     = (const float*)d_in[4];
    const float* Wxf      = (const float*)d_in[5];
    const float* Whf      = (const float*)d_in[6];
    const float* bf       = (const float*)d_in[7];
    const float* Wxb      = (const float*)d_in[8];
    const float* Whb      = (const float*)d_in[9];
    const float* bb       = (const float*)d_in[10];
    const int*   training = (const int*)  d_in[11];
    float* out = (float*)d_out;

    const int GSMEM = 256 * 132 * 4 + 256;            // epilogue staging (covers 2*STAGE2)
    cudaFuncSetAttribute(k_hgemm, cudaFuncAttributeMaxDynamicSharedMemorySize, GSMEM);
    cudaFuncSetAttribute(k_lstm, cudaFuncAttributeMaxDynamicSharedMemorySize, LSMEM);

    k_prepfin<<<16512, 256>>>(x, Wxf, Whf, Wxb, Whb, bf, bb,
                              lengths, scale, bias, training);
    k_bnapply<<<32768, 256>>>(x, mask, lengths, out);
    k_hgemm<<<dim3(16, 256, 2), 512, GSMEM>>>();
    k_lstm<<<128, 512, LSMEM>>>(out, lengths);         // launch idx 3 -> profiled
}

// round 16
// speedup vs baseline: 1.0593x; 1.0593x over previous
#include <cuda_runtime.h>
#include <cuda_bf16.h>
#include <cstdint>
#include <math.h>

#define TT    1024
#define BB    64
#define HH    512
#define HIDD  512
#define NG    2048           // 4*HID
#define NROWS 65536          // T*B

// ------------------------- scratch (static device memory; no allocs) -------------------------
// Z layout: [t][n-slice(64)][b(64)][40]  (32 gate-cols + 8 pad, per 8-hid slice)
static __device__ float d_Zf [(size_t)TT * 64 * 64 * 40];
static __device__ float d_Zb [(size_t)TT * 64 * 64 * 40];
static __device__ unsigned short d_Yh [(size_t)NROWS * HH];
static __device__ unsigned short d_Yl [(size_t)NROWS * HH];
static __device__ unsigned short d_Yrh[(size_t)NROWS * HH];
static __device__ unsigned short d_Yrl[(size_t)NROWS * HH];
static __device__ unsigned short d_Wxh[2][NG * HH];    // [n'][k] gate-interleaved bf16 hi
static __device__ unsigned short d_Wxl[2][NG * HH];    // lo
static __device__ unsigned short d_Whh[2][NG * HH];    // Wh bf16 hi
static __device__ unsigned short d_Whl[2][NG * HH];    // Wh bf16 lo
static __device__ float d_brd[2][NG];
// h transport: [dir][buf][4 chunks][hi 64x128 | lo 64x128] bf16, swizzled for ldmatrix
static __device__ unsigned short d_hA[2][2][65536];
static __device__ float d_ps [128 * 512];
static __device__ float d_ps2[128 * 512];
static __device__ float d_an[HH];
static __device__ float d_b2[HH];
static __device__ unsigned d_scnt;
static __device__ unsigned d_cnt[8][32];               // per (dir,chunk) publish counters, 128B-padded
static __device__ unsigned d_done;

// fast gate math: MUFU-based, safe at +/-inf (exp->inf => sigm->1/0, tanh->+/-1)
__device__ __forceinline__ float fsigm(float x) {
    return __fdividef(1.0f, 1.0f + __expf(-x));
}
__device__ __forceinline__ float ftanh(float x) {
    return 1.0f - __fdividef(2.0f, __expf(2.0f * x) + 1.0f);
}

__device__ __forceinline__ uint32_t smem_u32(const void* p) {
    uint32_t a;
    asm("{ .reg .u64 t; cvta.to.shared.u64 t, %1; cvt.u32.u64 %0, t; }" : "=r"(a) : "l"(p));
    return a;
}

__device__ __forceinline__ void cpa16(uint32_t dst, const void* src) {
    asm volatile("cp.async.cg.shared.global [%0], [%1], 16;" :: "r"(dst), "l"(src));
}
#define CPA_COMMIT() asm volatile("cp.async.commit_group;" ::: "memory")
#define CPA_WAIT1()  asm volatile("cp.async.wait_group 1;" ::: "memory")
#define CPA_WAIT0()  asm volatile("cp.async.wait_group 0;" ::: "memory")

__device__ __forceinline__ void ldsm4(uint32_t* d, uint32_t a) {
    asm volatile("ldmatrix.sync.aligned.m8n8.x4.shared.b16 {%0,%1,%2,%3}, [%4];"
                 : "=r"(d[0]), "=r"(d[1]), "=r"(d[2]), "=r"(d[3]) : "r"(a));
}
__device__ __forceinline__ void ldsm2(uint32_t* d, uint32_t a) {
    asm volatile("ldmatrix.sync.aligned.m8n8.x2.shared.b16 {%0,%1}, [%2];"
                 : "=r"(d[0]), "=r"(d[1]) : "r"(a));
}
__device__ __forceinline__ void mma16816(float* d, const uint32_t* a, const uint32_t* b) {
    asm volatile("mma.sync.aligned.m16n8k16.row.col.f32.bf16.bf16.f32 "
                 "{%0,%1,%2,%3}, {%4,%5,%6,%7}, {%8,%9}, {%0,%1,%2,%3};"
                 : "+f"(d[0]), "+f"(d[1]), "+f"(d[2]), "+f"(d[3])
                 : "r"(a[0]), "r"(a[1]), "r"(a[2]), "r"(a[3]), "r"(b[0]), "r"(b[1]));
}
__device__ __forceinline__ void redadd(float* p, float v) {
    asm volatile("red.global.add.f32 [%0], %1;" :: "l"(p), "f"(v) : "memory");
}
__device__ __forceinline__ void red_release_inc(unsigned* p) {
    asm volatile("red.release.gpu.global.add.u32 [%0], 1;" :: "l"(p) : "memory");
}

__device__ __forceinline__ void mbar_init(uint32_t m) {
    asm volatile("mbarrier.init.shared.b64 [%0], 1;" :: "r"(m) : "memory");
}
__device__ __forceinline__ void mbar_expect(uint32_t m, uint32_t bytes) {
    asm volatile("mbarrier.arrive.expect_tx.shared.b64 _, [%0], %1;"
                 :: "r"(m), "r"(bytes) : "memory");
}
__device__ __forceinline__ void mbar_wait(uint32_t m, uint32_t ph) {
    asm volatile(
        "{\n\t.reg .pred P;\n\tLW%=:\n\t"
        "mbarrier.try_wait.parity.acquire.cta.shared::cta.b64 P, [%0], %1;\n\t"
        "@!P bra LW%=;\n\t}"
        :: "r"(m), "r"(ph) : "memory");
}
__device__ __forceinline__ void bulk_g2s(uint32_t dst, const void* src, uint32_t bytes,
                                         uint32_t mbar) {
    asm volatile(
        "cp.async.bulk.shared::cluster.global.mbarrier::complete_tx::bytes [%0], [%1], %2, [%3];"
        :: "r"(dst), "l"(src), "r"(bytes), "r"(mbar) : "memory");
}

// ------------------- prepfin: stats partials + last-block finalize + weight reorder ----------
__global__ void k_prepfin(const float* __restrict__ x,
                          const float* __restrict__ Wxf, const float* __restrict__ Whf,
                          const float* __restrict__ Wxb, const float* __restrict__ Whb,
                          const float* __restrict__ bf,  const float* __restrict__ bb,
                          const int* __restrict__ lengths, const float* __restrict__ scale,
                          const float* __restrict__ bias, const int* __restrict__ training) {
    int bx = blockIdx.x, tid = threadIdx.x;     // 256 threads
    if (bx < 128) {
        size_t r0 = (size_t)bx * 512;
        float s0 = 0, s20 = 0, s1 = 0, s21 = 0;
        for (int r = 0; r < 512; r++) {
            float v0 = x[(r0 + r) * 512 + tid];
            float v1 = x[(r0 + r) * 512 + tid + 256];
            s0 += v0; s20 += v0 * v0;
            s1 += v1; s21 += v1 * v1;
        }
        d_ps [bx * 512 + tid]       = s0;
        d_ps [bx * 512 + tid + 256] = s1;
        d_ps2[bx * 512 + tid]       = s20;
        d_ps2[bx * 512 + tid + 256] = s21;
        __threadfence();
        __syncthreads();
        __shared__ int s_last;
        __shared__ float s_nz;
        if (tid == 0) {
            unsigned old = atomicAdd(&d_scnt, 1u);
            s_last = (old == 127u);
            if (s_last) {
                int s = 0;
                for (int b = 0; b < BB; b++) s += lengths[b];
                s_nz = (float)s;
            }
        }
        __syncthreads();
        if (s_last) {
            __threadfence();
            int tr = *training;
#pragma unroll
            for (int cc = 0; cc < 2; cc++) {
                int c = tid + cc * 256;
                float s = 0.0f, s2 = 0.0f;
#pragma unroll 4
                for (int p = 0; p < 128; p++) {
                    s  += d_ps [p * 512 + c];
                    s2 += d_ps2[p * 512 + c];
                }
                float mean, var;
                if (tr) {
                    mean = s / s_nz;
                    float m2 = s2 / s_nz;
                    var = fmaxf(0.0f, m2 - mean * mean);
                } else {
                    mean = 0.0f; var = 1.0f;
                }
                float a = rsqrtf(var + 1e-5f) * scale[c];
                d_an[c] = a;
                d_b2[c] = bias[c] - mean * a;
            }
            __syncthreads();
            if (tid == 0) { __threadfence(); d_scnt = 0u; }
        }
    } else {
        int idx = (bx - 128) * 256 + tid;       // [0, 4M)
        int z = idx >> 20;
        int i = idx & 0xFFFFF;
        const float* src = (z == 0) ? Wxf : (z == 1) ? Whf : (z == 2) ? Wxb : Whb;
        unsigned short* dh = (z == 0) ? d_Wxh[0] : (z == 1) ? d_Whh[0]
                           : (z == 2) ? d_Wxh[1] : d_Whh[1];
        unsigned short* dl = (z == 0) ? d_Wxl[0] : (z == 1) ? d_Whl[0]
                           : (z == 2) ? d_Wxl[1] : d_Whl[1];
        int k = i & 511, nn = i >> 9;
        int g = nn & 3, j = nn >> 2;
        float v = src[(k << 11) + (g << 9) + j];
        __nv_bfloat16 h = __float2bfloat16_rn(v);
        float lo = v - __bfloat162float(h);
        dh[i] = __bfloat16_as_ushort(h);
        dl[i] = __bfloat16_as_ushort(__float2bfloat16_rn(lo));
        if (i < NG) {
            if (z == 0) d_brd[0][i] = bf[((i & 3) << 9) + (i >> 2)];
            else if (z == 2) d_brd[1][i] = bb[((i & 3) << 9) + (i >> 2)];
        }
    }
}

// ------------------------- BN apply + mask + bf16 split + flip + out zero -------------------
__global__ void k_bnapply(const float* __restrict__ x, const float* __restrict__ mask,
                          const int* __restrict__ lengths, float* __restrict__ out) {
    int i = blockIdx.x * 256 + threadIdx.x;
    *(float4*)(out + (size_t)i * 4) = make_float4(0.f, 0.f, 0.f, 0.f);

    int row = i >> 7;
    int c4  = (i & 127) << 2;
    int t = row >> 6, b = row & 63;
    float4 xv = *(const float4*)(x + ((size_t)row << 9) + c4);
    float4 av = *(const float4*)(d_an + c4);
    float4 bv = *(const float4*)(d_b2 + c4);
    float m = __ldg(mask + row);
    float y[4];
    y[0] = (xv.x * av.x + bv.x) * m;
    y[1] = (xv.y * av.y + bv.y) * m;
    y[2] = (xv.z * av.z + bv.z) * m;
    y[3] = (xv.w * av.w + bv.w) * m;
    uint2 hv, lv;
    unsigned hs[4], ls[4];
#pragma unroll
    for (int q = 0; q < 4; q++) {
        __nv_bfloat16 h = __float2bfloat16_rn(y[q]);
        float lo = y[q] - __bfloat162float(h);
        hs[q] = __bfloat16_as_ushort(h);
        ls[q] = __bfloat16_as_ushort(__float2bfloat16_rn(lo));
    }
    hv.x = hs[0] | (hs[1] << 16); hv.y = hs[2] | (hs[3] << 16);
    lv.x = ls[0] | (ls[1] << 16); lv.y = ls[2] | (ls[3] << 16);
    size_t o = ((size_t)row << 9) + c4;
    *(uint2*)(d_Yh + o) = hv;
    *(uint2*)(d_Yl + o) = lv;
    int l = __ldg(lengths + b);
    if (t < l) {
        size_t orr = ((size_t)((l - 1 - t) * BB + b) << 9) + c4;
        *(uint2*)(d_Yrh + orr) = hv;
        *(uint2*)(d_Yrl + orr) = lv;
    } else {
        *(uint2*)(d_Yrh + o) = make_uint2(0u, 0u);
        *(uint2*)(d_Yrl + o) = make_uint2(0u, 0u);
    }
}

// ------------------------- HMMA split-bf16 GEMM: Z = Y@Wx + b (padded slice layout) ---------
#define STAGE 32768
__global__ __launch_bounds__(256) void k_hgemm() {
    extern __shared__ char dsm[];
    uint32_t sb = (smem_u32(dsm) + 127) & ~127u;
    float* cs = (float*)(dsm + (sb - smem_u32(dsm)));
    int tid = threadIdx.x;
    int lane = tid & 31, wid = tid >> 5;
    int wm0 = (wid & 1) * 64;
    int wn0 = (wid >> 1) * 32;
    int n0 = blockIdx.x * 128;
    int m0 = blockIdx.y * 128;
    int dir = blockIdx.z;

    const unsigned short* Ah = (dir ? d_Yrh : d_Yh) + (size_t)m0 * 512;
    const unsigned short* Al = (dir ? d_Yrl : d_Yl) + (size_t)m0 * 512;
    const unsigned short* Bh = d_Wxh[dir] + (size_t)n0 * 512;
    const unsigned short* Bl = d_Wxl[dir] + (size_t)n0 * 512;

    float acc[4][4][4];
#pragma unroll
    for (int a = 0; a < 4; a++)
#pragma unroll
        for (int b = 0; b < 4; b++)
#pragma unroll
            for (int c = 0; c < 4; c++) acc[a][b][c] = 0.0f;

    auto load_chunk = [&](int s, int k0) {
        uint32_t bA = sb + s * STAGE, bB = bA + 16384;
#pragma unroll
        for (int it = 0; it < 4; it++) {
            int q = tid + it * 256;
            int r = q >> 3, c = q & 7;
            uint32_t sw = (uint32_t)r * 128 + (uint32_t)((c ^ (r & 7)) << 4);
            cpa16(bA + sw, (c < 4) ? (const void*)(Ah + (size_t)r * 512 + k0 + c * 8)
                                   : (const void*)(Al + (size_t)r * 512 + k0 + (c - 4) * 8));
            cpa16(bB + sw, (c < 4) ? (const void*)(Bh + (size_t)r * 512 + k0 + c * 8)
                                   : (const void*)(Bl + (size_t)r * 512 + k0 + (c - 4) * 8));
        }
    };

    load_chunk(0, 0);  CPA_COMMIT();
    load_chunk(1, 32); CPA_COMMIT();

    for (int i = 0; i < 16; i++) {
        if (i < 15) CPA_WAIT1(); else CPA_WAIT0();
        __syncthreads();
        uint32_t bA = sb + (i & 1) * STAGE, bB = bA + 16384;
#pragma unroll
        for (int ks = 0; ks < 2; ks++) {
            uint32_t ah[4][4], al[4][4];
#pragma unroll
            for (int mf = 0; mf < 4; mf++) {
                int r = wm0 + mf * 16 + (lane & 15);
                int ch = 2 * ks + (lane >> 4);
                ldsm4(ah[mf], bA + r * 128 + ((ch       ^ (r & 7)) << 4));
                ldsm4(al[mf], bA + r * 128 + (((ch + 4) ^ (r & 7)) << 4));
            }
#pragma unroll
            for (int nf = 0; nf < 4; nf++) {
                int rb = wn0 + nf * 8 + (lane & 7);
                int cb = 2 * ks + ((lane >> 3) & 1);
                uint32_t bh[2], bl[2];
                ldsm2(bh, bB + rb * 128 + ((cb       ^ (rb & 7)) << 4));
                ldsm2(bl, bB + rb * 128 + (((cb + 4) ^ (rb & 7)) << 4));
#pragma unroll
                for (int mf = 0; mf < 4; mf++) {
                    mma16816(acc[mf][nf], ah[mf], bh);
                    mma16816(acc[mf][nf], ah[mf], bl);
                    mma16816(acc[mf][nf], al[mf], bh);
                }
            }
        }
        __syncthreads();
        if (i + 2 < 16) { load_chunk(i & 1, (i + 2) * 32); CPA_COMMIT(); }
    }

    const float* bias = d_brd[dir];
#pragma unroll
    for (int nf = 0; nf < 4; nf++) {
        int gc = wn0 + nf * 8 + (lane & 3) * 2;
        float b0 = __ldg(bias + n0 + gc), b1 = __ldg(bias + n0 + gc + 1);
#pragma unroll
        for (int mf = 0; mf < 4; mf++) {
            int r = wm0 + mf * 16 + (lane >> 2);
            cs[r * 132 + gc]             = acc[mf][nf][0] + b0;
            cs[r * 132 + gc + 1]         = acc[mf][nf][1] + b1;
            cs[(r + 8) * 132 + gc]       = acc[mf][nf][2] + b0;
            cs[(r + 8) * 132 + gc + 1]   = acc[mf][nf][3] + b1;
        }
    }
    __syncthreads();

    float* Z = dir ? d_Zb : d_Zf;
    int t0 = m0 >> 6;
    int nb0 = n0 >> 5;
#pragma unroll
    for (int p = 0; p < 16; p++) {
        int q = tid + p * 256;
        int c4i = q & 7;
        int nq  = (q >> 3) & 3;
        int b   = (q >> 5) & 63;
        int th  = q >> 11;
        float4 v = *(const float4*)(cs + (th * 64 + b) * 132 + nq * 32 + c4i * 4);
        *(float4*)(Z + ((size_t)(t0 + th) * 64 + nb0 + nq) * 2560 + b * 40 + c4i * 4) = v;
    }
}

// ------------------------- persistent LSTM v11: hi-first split DMA pipeline -----------------
// Per chunk: hi 16KB (own mbar) then lo 16KB (own mbar). MMA: wait-hi -> ah*bh + ah*bl
// (keeping bh regs) -> wait-lo -> al*bh (reusing bh regs).
// mbars: A-hi [4] @ mb+0..31, A-lo [4] @ mb+32..63, z [2] @ mb+64..79
#define LSMEM (226304 + 96)
__global__ __launch_bounds__(512) void k_lstm(float* __restrict__ out,
                                              const int* __restrict__ lengths) {
    extern __shared__ char sm[];
    uint32_t smb = smem_u32(sm);
    float* zacc = (float*)(sm + 217088);
    uint32_t mb = smb + 226304;

    int blk = blockIdx.x;
    int dir = blk >> 6;
    int n   = blk & 63;
    const float* __restrict__ Zx = dir ? d_Zb : d_Zf;

    int tid = threadIdx.x;
    int lane = tid & 31, w = tid >> 5;
    int mt = w & 3, nt = w >> 2;

    int tx = tid & 7;
    int ty = (tid >> 3) & 31;
    int j = n * 8 + tx;
    int r0 = ty * 2;
    int l0 = __ldg(lengths + r0);
    int l1 = __ldg(lengths + r0 + 1);

    // ---- load Wh (bf16 hi/lo) into swizzled smem B, once ----
    for (int i = tid; i < 2048; i += 512) {
        int c = i >> 6, kc = i & 63;
        int segp = (kc & ~7) | ((kc & 7) ^ (c & 7));
        const uint4* sh = (const uint4*)(d_Whh[dir] + ((size_t)(n * 32 + c) * 512 + kc * 8));
        const uint4* sl = (const uint4*)(d_Whl[dir] + ((size_t)(n * 32 + c) * 512 + kc * 8));
        *(uint4*)(sm + c * 1024 + segp * 16)         = *sh;
        *(uint4*)(sm + 32768 + c * 1024 + segp * 16) = *sl;
    }
    if (tid == 0) {
#pragma unroll
        for (int c = 0; c < 10; c++) mbar_init(mb + c * 8);
    }
    __syncthreads();

    if (tid == 0) {                                   // z(0) prefetch
        mbar_expect(mb + 64, 10240);
        bulk_g2s(smb + 196608, Zx + (size_t)n * 2560, 10240, mb + 64);
    }

    float cst0 = 0.0f, cst1 = 0.0f;

    // producer swizzle constants
    int segP0 = (n & 8) | ((n & 7) ^ (r0 & 7));
    int segP1 = (n & 8) | ((n & 7) ^ ((r0 + 1) & 7));
    int pchunk = (n >> 4) * 16384;
    unsigned* mycnt = &d_cnt[dir * 4 + (n >> 4)][0];

    for (int t = 0; t < TT; t++) {
        // parallel per-chunk gating + split DMA issue (threads 0-3), z prefetch (thread 4)
        if (t > 0 && tid < 4) {
            const unsigned* cp = &d_cnt[dir * 4 + tid][0];
            unsigned need = (unsigned)t * 16u;
            unsigned v;
            do {
                asm volatile("ld.acquire.gpu.u32 %0, [%1];" : "=r"(v) : "l"(cp) : "memory");
            } while (v < need);
            const unsigned short* hsrc = d_hA[dir][(t - 1) & 1] + tid * 16384;
            uint32_t dst = smb + 65536 + tid * 32768;
            mbar_expect(mb + tid * 8, 16384);
            bulk_g2s(dst, hsrc, 16384, mb + tid * 8);                      // hi first
            mbar_expect(mb + 32 + tid * 8, 16384);
            bulk_g2s(dst + 16384, hsrc + 8192, 16384, mb + 32 + tid * 8);  // lo second
        }
        if (tid == 4 && t + 1 < TT) {
            int s = (t + 1) & 1;
            mbar_expect(mb + 64 + s * 8, 10240);
            bulk_g2s(smb + 196608 + s * 10240,
                     Zx + ((size_t)(t + 1) * 64 + n) * 2560, 10240, mb + 64 + s * 8);
        }

        // ---- MMA phase (all 16 warps) ----
        if (t > 0) {
            float acc[4] = {0.f, 0.f, 0.f, 0.f};
            int r  = mt * 16 + (lane & 15);
            int cB = nt * 8 + (lane & 7);
            uint32_t rowA = smb + 65536 + (uint32_t)r * 256;
            uint32_t rowB = smb + (uint32_t)cB * 1024;
            uint32_t ph = (uint32_t)((t - 1) & 1);
#pragma unroll
            for (int c = 0; c < 4; c++) {
                uint32_t aHi = rowA + c * 32768;
                uint32_t aLo = aHi + 16384;
                uint32_t bh_all[16];
                // pass 1: hi terms (ah*bh, ah*bl), keep bh in regs
                mbar_wait(mb + c * 8, ph);
#pragma unroll
                for (int kt2 = 0; kt2 < 4; kt2++) {
                    int kcB = c * 16 + 4 * kt2 + (lane >> 3);
                    uint32_t segB = (uint32_t)((kcB & ~7) | ((kcB & 7) ^ (cB & 7))) << 4;
                    uint32_t bl[4];
                    ldsm4(bh_all + kt2 * 4, rowB + segB);
                    ldsm4(bl, rowB + 32768 + segB);
#pragma unroll
                    for (int ss = 0; ss < 2; ss++) {
                        int kcA = 4 * kt2 + 2 * ss + (lane >> 4);
                        uint32_t segA = (uint32_t)((kcA & 8) | ((kcA & 7) ^ (r & 7))) << 4;
                        uint32_t ah[4];
                        ldsm4(ah, aHi + segA);
                        mma16816(acc, ah, bh_all + kt2 * 4 + 2 * ss);
                        mma16816(acc, ah, bl + 2 * ss);
                    }
                }
                // pass 2: lo term (al*bh), bh reused from regs
                mbar_wait(mb + 32 + c * 8, ph);
#pragma unroll
                for (int kt2 = 0; kt2 < 4; kt2++) {
#pragma unroll
                    for (int ss = 0; ss < 2; ss++) {
                        int kcA = 4 * kt2 + 2 * ss + (lane >> 4);
                        uint32_t segA = (uint32_t)((kcA & 8) | ((kcA & 7) ^ (r & 7))) << 4;
                        uint32_t al[4];
                        ldsm4(al, aLo + segA);
                        mma16816(acc, al, bh_all + kt2 * 4 + 2 * ss);
                    }
                }
            }
            int rr = mt * 16 + (lane >> 2);
            int cc = nt * 8 + (lane & 3) * 2;
            *(float2*)(zacc + rr * 36 + cc)       = make_float2(acc[0], acc[1]);
            *(float2*)(zacc + (rr + 8) * 36 + cc) = make_float2(acc[2], acc[3]);
        }
        __syncthreads();

        // ---- epilogue (tid < 256) ----
        float hn0 = 0.f, hn1 = 0.f;
        if (tid < 256) {
            mbar_wait(mb + 64 + (t & 1) * 8, (uint32_t)((t >> 1) & 1));
            const float* zb = (const float*)(sm + 196608) + (t & 1) * 2560;
            float4 zf0 = *(const float4*)(zb + r0 * 40 + tx * 4);
            float4 zf1 = *(const float4*)(zb + (r0 + 1) * 40 + tx * 4);
            float4 zaA, zaB;
            if (t > 0) {
                zaA = *(const float4*)(zacc + r0 * 36 + tx * 4);
                zaB = *(const float4*)(zacc + (r0 + 1) * 36 + tx * 4);
            } else {
                zaA = make_float4(0.f, 0.f, 0.f, 0.f);
                zaB = zaA;
            }
            {
                float zi = zaA.x + zf0.x;
                float zf = zaA.y + zf0.y;
                float zg = zaA.z + zf0.z;
                float zo = zaA.w + zf0.w;
                float cn = fsigm(zf) * cst0 + fsigm(zi) * ftanh(zg);
                cst0 = cn;
                hn0 = fsigm(zo) * ftanh(cn);
            }
            {
                float zi = zaB.x + zf1.x;
                float zf = zaB.y + zf1.y;
                float zg = zaB.z + zf1.z;
                float zo = zaB.w + zf1.w;
                float cn = fsigm(zf) * cst1 + fsigm(zi) * ftanh(zg);
                cst1 = cn;
                hn1 = fsigm(zo) * ftanh(cn);
            }

            // publish h(t+1): bf16 hi/lo into pre-swizzled transport buffer
            unsigned short* hw = d_hA[dir][t & 1] + pchunk;
            __nv_bfloat16 h0 = __float2bfloat16_rn(hn0);
            __nv_bfloat16 h1 = __float2bfloat16_rn(hn1);
            float lo0 = hn0 - __bfloat162float(h0);
            float lo1 = hn1 - __bfloat162float(h1);
            hw[r0 * 128 + segP0 * 8 + tx]              = __bfloat16_as_ushort(h0);
            hw[(r0 + 1) * 128 + segP1 * 8 + tx]        = __bfloat16_as_ushort(h1);
            hw[8192 + r0 * 128 + segP0 * 8 + tx]       = __bfloat16_as_ushort(__float2bfloat16_rn(lo0));
            hw[8192 + (r0 + 1) * 128 + segP1 * 8 + tx] = __bfloat16_as_ushort(__float2bfloat16_rn(lo1));
        }

        // publish counter: bar.sync orders intra-CTA; release-atomic orders inter-CTA
        __syncthreads();
        if (tid == 0) red_release_inc(mycnt);

        // output accumulation off the critical path (no-return reductions)
        if (tid < 256) {
            if (dir == 0) {
                redadd(out + ((size_t)(t * BB + r0)) * HIDD + j, hn0);
                redadd(out + ((size_t)(t * BB + r0 + 1)) * HIDD + j, hn1);
            } else {
                int to0 = (t < l0) ? (l0 - 1 - t) : (TT - 1 + l0 - t);
                int to1 = (t < l1) ? (l1 - 1 - t) : (TT - 1 + l1 - t);
                redadd(out + ((size_t)(to0 * BB + r0)) * HIDD + j, hn0);
                redadd(out + ((size_t)(to1 * BB + r0 + 1)) * HIDD + j, hn1);
            }
        }
    }

    // self-reset for graph replay
    __syncthreads();
    if (tid == 0) {
        __threadfence();
        atomicAdd(&d_done, 1u);
        if (blk == 0) {
            volatile unsigned* vd = &d_done;
            while (*vd < 128u) { }
            for (int q = 0; q < 8; q++) d_cnt[q][0] = 0u;
            __threadfence();
            d_done = 0u;
        }
    }
}

// ------------------------- launch -------------------------
extern "C" void kernel_launch(void* const* d_in, const int* in_sizes, int n_in,
                              void* d_out, int out_size) {
    const float* x        = (const float*)d_in[0];
    const int*   lengths  = (const int*)  d_in[1];
    const float* mask     = (const float*)d_in[2];
    const float* scale    = (const float*)d_in[3];
    const float* bias     = (const float*)d_in[4];
    const float* Wxf      = (const float*)d_in[5];
    const float* Whf      = (const float*)d_in[6];
    const float* bf       = (const float*)d_in[7];
    const float* Wxb      = (const float*)d_in[8];
    const float* Whb      = (const float*)d_in[9];
    const float* bb       = (const float*)d_in[10];
    const int*   training = (const int*)  d_in[11];
    float* out = (float*)d_out;

    const int GSMEM = 128 * 132 * 4 + 256;
    cudaFuncSetAttribute(k_hgemm, cudaFuncAttributeMaxDynamicSharedMemorySize, GSMEM);
    cudaFuncSetAttribute(k_lstm, cudaFuncAttributeMaxDynamicSharedMemorySize, LSMEM);

    k_prepfin<<<16512, 256>>>(x, Wxf, Whf, Wxb, Whb, bf, bb,
                              lengths, scale, bias, training);
    k_bnapply<<<32768, 256>>>(x, mask, lengths, out);
    k_hgemm<<<dim3(16, 512, 2), 256, GSMEM>>>();
    k_lstm<<<128, 512, LSMEM>>>(out, lengths);         // launch idx 3 -> profiled
}